// round 6
// baseline (speedup 1.0000x reference)
#include <cuda_runtime.h>

#define D 128
#define DV 32            // float4 per row
#define BM 128           // gemm rows per block
#define LDW 136          // padded smem stride (floats): conflict-free B frags
#define MAXN 100352
#define MAXE 1700000

// ---------------- scratch (device globals: no allocation allowed) -------------
__device__ float g_h[MAXN * D];
__device__ float g_x[MAXN * D];
__device__ float g_y[MAXN * D];
__device__ float g_dinv[MAXN];
__device__ int   g_deg[MAXN];
__device__ int   g_rowstart[MAXN + 1];
__device__ int   g_cursor[MAXN];
__device__ int   g_csr_src[MAXE];
__device__ float g_csr_norm[MAXE];
__device__ int   g_part[64];

// ---------------- degree / normalization ------------------------------------
__global__ void zero_deg_kernel(int n) {
    int i = blockIdx.x * blockDim.x + threadIdx.x;
    if (i < n) g_deg[i] = 0;
}

__global__ void count_deg_kernel(const int* __restrict__ dst, int E) {
    int e = blockIdx.x * blockDim.x + threadIdx.x;
    if (e < E) atomicAdd(&g_deg[dst[e]], 1);
}

__global__ void dinv_kernel(int n) {
    int i = blockIdx.x * blockDim.x + threadIdx.x;
    if (i < n) g_dinv[i] = rsqrtf((float)(g_deg[i] + 1));
}

// ---- multi-block scan: pass 1, per-block (4096 elems) partial sums ----------
__global__ void scan_part_kernel(int n) {
    int base = blockIdx.x * 4096;
    int sum = 0;
    for (int i = threadIdx.x; i < 4096; i += 256) {
        int idx = base + i;
        if (idx < n) sum += g_deg[idx];
    }
    #pragma unroll
    for (int o = 16; o > 0; o >>= 1) sum += __shfl_xor_sync(0xffffffffu, sum, o);
    __shared__ int ws[8];
    if ((threadIdx.x & 31) == 0) ws[threadIdx.x >> 5] = sum;
    __syncthreads();
    if (threadIdx.x == 0) {
        int t = 0;
        #pragma unroll
        for (int w = 0; w < 8; ++w) t += ws[w];
        g_part[blockIdx.x] = t;
    }
}

// ---- pass 2: per-block exclusive scan of its 4096 chunk + global offset -----
__global__ void scan_final_kernel(int n, int nblocks) {
    __shared__ int s_off;
    __shared__ int warp_sums[32];
    int tid = threadIdx.x;                  // 1024 threads
    int base = blockIdx.x * 4096;
    if (tid == 0) {
        int off = 0;
        for (int b = 0; b < blockIdx.x; ++b) off += g_part[b];
        s_off = off;
        if (blockIdx.x == 0) {
            int tot = 0;
            for (int b = 0; b < nblocks; ++b) tot += g_part[b];
            g_rowstart[n] = tot;
        }
    }
    __syncthreads();

    int i0 = base + tid * 4;
    int v[4];
    int s = 0;
    #pragma unroll
    for (int k = 0; k < 4; ++k) {
        int idx = i0 + k;
        v[k] = (idx < n) ? g_deg[idx] : 0;
        s += v[k];
    }
    int lane = tid & 31, wid = tid >> 5;
    int x = s;
    #pragma unroll
    for (int o = 1; o < 32; o <<= 1) {
        int y = __shfl_up_sync(0xffffffffu, x, o);
        if (lane >= o) x += y;
    }
    if (lane == 31) warp_sums[wid] = x;
    __syncthreads();
    if (wid == 0) {
        int w = warp_sums[lane];
        #pragma unroll
        for (int o = 1; o < 32; o <<= 1) {
            int y = __shfl_up_sync(0xffffffffu, w, o);
            if (lane >= o) w += y;
        }
        warp_sums[lane] = w;
    }
    __syncthreads();
    int excl = x - s + ((wid > 0) ? warp_sums[wid - 1] : 0) + s_off;
    #pragma unroll
    for (int k = 0; k < 4; ++k) {
        int idx = i0 + k;
        if (idx < n) {
            g_rowstart[idx] = excl;
            g_cursor[idx]   = excl;
            excl += v[k];
        }
    }
}

__global__ void fill_kernel(const int* __restrict__ src, const int* __restrict__ dst, int E) {
    int e = blockIdx.x * blockDim.x + threadIdx.x;
    if (e >= E) return;
    int u = src[e], v = dst[e];
    int slot = atomicAdd(&g_cursor[v], 1);
    g_csr_src[slot]  = u;
    g_csr_norm[slot] = g_dinv[u] * g_dinv[v];
}

// ---------------- TF32 mma.sync GEMM with hi/lo compensation -----------------
// out = X @ W (+epilogues).  epi: 0=none; 1=relu(acc+bias); 2=acc+bias+add[row]
// acc += Ahi*Bhi + Ahi*Blo + Alo*Bhi  (rel err ~1e-6)
__device__ __forceinline__ void mma_tf32(float* d, unsigned a0, unsigned a1,
                                         unsigned a2, unsigned a3,
                                         unsigned b0, unsigned b1) {
    asm volatile(
        "mma.sync.aligned.m16n8k8.row.col.f32.tf32.tf32.f32 "
        "{%0,%1,%2,%3}, {%4,%5,%6,%7}, {%8,%9}, {%0,%1,%2,%3};"
        : "+f"(d[0]), "+f"(d[1]), "+f"(d[2]), "+f"(d[3])
        : "r"(a0), "r"(a1), "r"(a2), "r"(a3), "r"(b0), "r"(b1));
}

__device__ __forceinline__ void split_bits(float v, unsigned& hi, unsigned& lo) {
    hi = __float_as_uint(v) & 0xFFFFE000u;
    lo = __float_as_uint(v - __uint_as_float(hi));
}

__global__ void gemm_kernel(const float* __restrict__ X, const float* __restrict__ W,
                            const float* __restrict__ bias, const float* __restrict__ add,
                            float* __restrict__ out, int M, int epi) {
    extern __shared__ float sm[];
    float* Ws = sm;               // 128 x LDW
    float* Xs = sm + D * LDW;     // 128 x LDW (reused as Obuf after mainloop)

    int row0 = blockIdx.x * BM;
    int tid  = threadIdx.x;
    int wid  = tid >> 5;
    int lane = tid & 31;
    int quad = lane >> 2;         // 0..7
    int qt   = lane & 3;          // 0..3

    // stage W (full 128x128) into padded smem, coalesced
    const float4* W4 = (const float4*)W;
    for (int i = tid; i < D * DV; i += 256) {
        int r = i >> 5, c4 = i & 31;
        *(float4*)(Ws + r * LDW + c4 * 4) = W4[r * DV + c4];
    }
    // stage X tile (guard rows)
    const float4* X4 = (const float4*)X;
    for (int i = tid; i < BM * DV; i += 256) {
        int r = i >> 5, c4 = i & 31;
        int gr = row0 + r;
        float4 v = make_float4(0.f, 0.f, 0.f, 0.f);
        if (gr < M) v = X4[gr * DV + c4];
        *(float4*)(Xs + r * LDW + c4 * 4) = v;
    }
    __syncthreads();

    // warp computes rows [wid*16, wid*16+16) x all 128 cols (16 n-tiles)
    float acc[16][4];
    #pragma unroll
    for (int nt = 0; nt < 16; ++nt)
        #pragma unroll
        for (int j = 0; j < 4; ++j) acc[nt][j] = 0.f;

    const float* xb0 = Xs + (wid * 16 + quad) * LDW + qt;
    const float* xb1 = xb0 + 8 * LDW;

    for (int ks = 0; ks < 16; ++ks) {
        int k0 = ks * 8;
        float a0f = xb0[k0], a2f = xb0[k0 + 4];
        float a1f = xb1[k0], a3f = xb1[k0 + 4];
        unsigned ah0, al0, ah1, al1, ah2, al2, ah3, al3;
        split_bits(a0f, ah0, al0);
        split_bits(a1f, ah1, al1);
        split_bits(a2f, ah2, al2);
        split_bits(a3f, ah3, al3);

        const float* wk0 = Ws + (k0 + qt) * LDW + quad;       // b0: k row
        const float* wk1 = wk0 + 4 * LDW;                      // b1: k+4 row
        #pragma unroll
        for (int nt = 0; nt < 16; ++nt) {
            float b0f = wk0[nt * 8];
            float b1f = wk1[nt * 8];
            unsigned bh0, bl0, bh1, bl1;
            split_bits(b0f, bh0, bl0);
            split_bits(b1f, bh1, bl1);
            mma_tf32(acc[nt], ah0, ah1, ah2, ah3, bh0, bh1);
            mma_tf32(acc[nt], ah0, ah1, ah2, ah3, bl0, bl1);
            mma_tf32(acc[nt], al0, al1, al2, al3, bh0, bh1);
        }
    }
    __syncthreads();   // everyone done reading Xs

    // stash accumulators into Xs (as Obuf) for a clean coalesced epilogue
    {
        float* ob0 = Xs + (wid * 16 + quad) * LDW + 2 * qt;
        float* ob1 = ob0 + 8 * LDW;
        #pragma unroll
        for (int nt = 0; nt < 16; ++nt) {
            *(float2*)(ob0 + nt * 8) = make_float2(acc[nt][0], acc[nt][1]);
            *(float2*)(ob1 + nt * 8) = make_float2(acc[nt][2], acc[nt][3]);
        }
    }
    __syncthreads();

    const float4* add4 = (const float4*)add;
    float4* out4 = (float4*)out;
    for (int i = tid; i < BM * DV; i += 256) {
        int r = i >> 5, c4 = i & 31;
        int gr = row0 + r;
        if (gr >= M) continue;
        float4 o = *(float4*)(Xs + r * LDW + c4 * 4);
        if (epi != 0) {
            float4 b = ((const float4*)bias)[c4];
            o.x += b.x; o.y += b.y; o.z += b.z; o.w += b.w;
        }
        if (epi == 1) {
            o.x = fmaxf(o.x, 0.f); o.y = fmaxf(o.y, 0.f);
            o.z = fmaxf(o.z, 0.f); o.w = fmaxf(o.w, 0.f);
        } else if (epi == 2) {
            float4 a = add4[gr * DV + c4];
            o.x += a.x; o.y += a.y; o.z += a.z; o.w += a.w;
        }
        out4[gr * DV + c4] = o;
    }
}

// ---------------- fused aggregation + bias + LayerNorm (+ReLU) ---------------
// warp per node: out[v] = LN( dinv[v]^2*h[v] + sum_in norm*h[u] + bias )
__global__ void agg_ln_kernel(const float* __restrict__ h, const float* __restrict__ bias,
                              const float* __restrict__ gamma, const float* __restrict__ beta,
                              float* __restrict__ out, int N, int doRelu) {
    int gw   = (blockIdx.x * blockDim.x + threadIdx.x) >> 5;
    int lane = threadIdx.x & 31;
    if (gw >= N) return;
    int v = gw;

    const float4* h4 = (const float4*)h;
    float dv = g_dinv[v];
    float ds = dv * dv;
    float4 acc = h4[v * DV + lane];
    acc.x *= ds; acc.y *= ds; acc.z *= ds; acc.w *= ds;

    int s = g_rowstart[v];
    int e = g_rowstart[v + 1];
    for (int j = s; j < e; ++j) {
        int u   = g_csr_src[j];
        float n = g_csr_norm[j];
        float4 hv = h4[u * DV + lane];
        acc.x += hv.x * n; acc.y += hv.y * n;
        acc.z += hv.z * n; acc.w += hv.w * n;
    }

    float4 bv = ((const float4*)bias)[lane];
    acc.x += bv.x; acc.y += bv.y; acc.z += bv.z; acc.w += bv.w;

    // mean over 128
    float sum = acc.x + acc.y + acc.z + acc.w;
    #pragma unroll
    for (int o = 16; o > 0; o >>= 1) sum += __shfl_xor_sync(0xffffffffu, sum, o);
    float mu = sum * (1.0f / 128.0f);

    float cx = acc.x - mu, cy = acc.y - mu, cz = acc.z - mu, cw = acc.w - mu;
    float sq = cx * cx + cy * cy + cz * cz + cw * cw;
    #pragma unroll
    for (int o = 16; o > 0; o >>= 1) sq += __shfl_xor_sync(0xffffffffu, sq, o);
    float rs = rsqrtf(sq * (1.0f / 128.0f) + 1e-5f);

    float4 gv  = ((const float4*)gamma)[lane];
    float4 bev = ((const float4*)beta)[lane];
    float4 o;
    o.x = cx * rs * gv.x + bev.x;
    o.y = cy * rs * gv.y + bev.y;
    o.z = cz * rs * gv.z + bev.z;
    o.w = cw * rs * gv.w + bev.w;
    if (doRelu) {
        o.x = fmaxf(o.x, 0.f); o.y = fmaxf(o.y, 0.f);
        o.z = fmaxf(o.z, 0.f); o.w = fmaxf(o.w, 0.f);
    }
    ((float4*)out)[v * DV + lane] = o;
}

// ---------------- driver -----------------------------------------------------
extern "C" void kernel_launch(void* const* d_in, const int* in_sizes, int n_in,
                              void* d_out, int out_size) {
    const int*   edge_index = (const int*)d_in[0];
    const float* ent = (const float*)d_in[1];
    const float* W1  = (const float*)d_in[2];
    const float* b1  = (const float*)d_in[3];
    const float* g1  = (const float*)d_in[4];
    const float* be1 = (const float*)d_in[5];
    const float* W2  = (const float*)d_in[6];
    const float* b2  = (const float*)d_in[7];
    const float* g2  = (const float*)d_in[8];
    const float* be2 = (const float*)d_in[9];
    const float* W3  = (const float*)d_in[10];
    const float* b3  = (const float*)d_in[11];
    const float* g3  = (const float*)d_in[12];
    const float* be3 = (const float*)d_in[13];
    const float* Wt1 = (const float*)d_in[14];
    const float* bt1 = (const float*)d_in[15];
    const float* Wt2 = (const float*)d_in[16];
    const float* bt2 = (const float*)d_in[17];

    int E = in_sizes[0] / 2;
    int N = in_sizes[1] / D;
    const int* src = edge_index;
    const int* dst = edge_index + E;

    float *ph, *px, *py;
    cudaGetSymbolAddress((void**)&ph, g_h);
    cudaGetSymbolAddress((void**)&px, g_x);
    cudaGetSymbolAddress((void**)&py, g_y);

    const int SMEM = 2 * D * LDW * sizeof(float);   // 2*128*136*4 = 139264 B
    cudaFuncSetAttribute(gemm_kernel, cudaFuncAttributeMaxDynamicSharedMemorySize, SMEM);

    int nb  = (N + 255) / 256;
    int eb  = (E + 255) / 256;
    int gg  = (N + BM - 1) / BM;
    int ab  = (N * 32 + 255) / 256;
    int sb  = (N + 4095) / 4096;

    // graph preprocessing (CSR by dst, symmetric normalization)
    zero_deg_kernel<<<nb, 256>>>(N);
    count_deg_kernel<<<eb, 256>>>(dst, E);
    dinv_kernel<<<nb, 256>>>(N);
    scan_part_kernel<<<sb, 256>>>(N);
    scan_final_kernel<<<sb, 1024>>>(N, sb);
    fill_kernel<<<eb, 256>>>(src, dst, E);

    // layer 1
    gemm_kernel<<<gg, 256, SMEM>>>(ent, W1, nullptr, nullptr, ph, N, 0);
    agg_ln_kernel<<<ab, 256>>>(ph, b1, g1, be1, px, N, 1);
    // layer 2
    gemm_kernel<<<gg, 256, SMEM>>>(px, W2, nullptr, nullptr, ph, N, 0);
    agg_ln_kernel<<<ab, 256>>>(ph, b2, g2, be2, py, N, 1);
    // layer 3 (LN, no relu)
    gemm_kernel<<<gg, 256, SMEM>>>(py, W3, nullptr, nullptr, ph, N, 0);
    agg_ln_kernel<<<ab, 256>>>(ph, b3, g3, be3, px, N, 0);
    // transform MLP + residual with x0
    gemm_kernel<<<gg, 256, SMEM>>>(px, Wt1, bt1, nullptr, py, N, 1);
    gemm_kernel<<<gg, 256, SMEM>>>(py, Wt2, bt2, ent, (float*)d_out, N, 2);
}

// round 7
// speedup vs baseline: 1.0035x; 1.0035x over previous
#include <cuda_runtime.h>

#define D 128
#define DV 32            // float4 per row
#define BM 128           // gemm rows per block
#define LDW 136          // padded smem stride (floats): conflict-free B frags
#define MAXN 100352
#define MAXE 1700000

// ---------------- scratch (device globals: no allocation allowed) -------------
__device__ float g_h[MAXN * D];
__device__ float g_x[MAXN * D];
__device__ float g_y[MAXN * D];
__device__ float g_dinv[MAXN];
__device__ int   g_deg[MAXN];
__device__ int   g_rowstart[MAXN + 1];
__device__ int   g_cursor[MAXN];
__device__ int   g_csr_src[MAXE];
__device__ float g_csr_norm[MAXE];
__device__ int   g_part[64];

// ---------------- degree / normalization ------------------------------------
__global__ void zero_deg_kernel(int n) {
    int i = blockIdx.x * blockDim.x + threadIdx.x;
    if (i < n) g_deg[i] = 0;
}

__global__ void count_deg_kernel(const int* __restrict__ dst, int E) {
    int e = blockIdx.x * blockDim.x + threadIdx.x;
    if (e < E) atomicAdd(&g_deg[dst[e]], 1);
}

__global__ void dinv_kernel(int n) {
    int i = blockIdx.x * blockDim.x + threadIdx.x;
    if (i < n) g_dinv[i] = rsqrtf((float)(g_deg[i] + 1));
}

// ---- multi-block scan: pass 1, per-block (4096 elems) partial sums ----------
__global__ void scan_part_kernel(int n) {
    int base = blockIdx.x * 4096;
    int sum = 0;
    for (int i = threadIdx.x; i < 4096; i += 256) {
        int idx = base + i;
        if (idx < n) sum += g_deg[idx];
    }
    #pragma unroll
    for (int o = 16; o > 0; o >>= 1) sum += __shfl_xor_sync(0xffffffffu, sum, o);
    __shared__ int ws[8];
    if ((threadIdx.x & 31) == 0) ws[threadIdx.x >> 5] = sum;
    __syncthreads();
    if (threadIdx.x == 0) {
        int t = 0;
        #pragma unroll
        for (int w = 0; w < 8; ++w) t += ws[w];
        g_part[blockIdx.x] = t;
    }
}

// ---- pass 2: per-block exclusive scan of its 4096 chunk + global offset -----
__global__ void scan_final_kernel(int n, int nblocks) {
    __shared__ int s_off;
    __shared__ int warp_sums[32];
    int tid = threadIdx.x;                  // 1024 threads
    int base = blockIdx.x * 4096;
    if (tid == 0) {
        int off = 0;
        for (int b = 0; b < blockIdx.x; ++b) off += g_part[b];
        s_off = off;
        if (blockIdx.x == 0) {
            int tot = 0;
            for (int b = 0; b < nblocks; ++b) tot += g_part[b];
            g_rowstart[n] = tot;
        }
    }
    __syncthreads();

    int i0 = base + tid * 4;
    int v[4];
    int s = 0;
    #pragma unroll
    for (int k = 0; k < 4; ++k) {
        int idx = i0 + k;
        v[k] = (idx < n) ? g_deg[idx] : 0;
        s += v[k];
    }
    int lane = tid & 31, wid = tid >> 5;
    int x = s;
    #pragma unroll
    for (int o = 1; o < 32; o <<= 1) {
        int y = __shfl_up_sync(0xffffffffu, x, o);
        if (lane >= o) x += y;
    }
    if (lane == 31) warp_sums[wid] = x;
    __syncthreads();
    if (wid == 0) {
        int w = warp_sums[lane];
        #pragma unroll
        for (int o = 1; o < 32; o <<= 1) {
            int y = __shfl_up_sync(0xffffffffu, w, o);
            if (lane >= o) w += y;
        }
        warp_sums[lane] = w;
    }
    __syncthreads();
    int excl = x - s + ((wid > 0) ? warp_sums[wid - 1] : 0) + s_off;
    #pragma unroll
    for (int k = 0; k < 4; ++k) {
        int idx = i0 + k;
        if (idx < n) {
            g_rowstart[idx] = excl;
            g_cursor[idx]   = excl;
            excl += v[k];
        }
    }
}

__global__ void fill_kernel(const int* __restrict__ src, const int* __restrict__ dst, int E) {
    int e = blockIdx.x * blockDim.x + threadIdx.x;
    if (e >= E) return;
    int u = src[e], v = dst[e];
    int slot = atomicAdd(&g_cursor[v], 1);
    g_csr_src[slot]  = u;
    g_csr_norm[slot] = g_dinv[u] * g_dinv[v];
}

// ---------------- TF32 mma.sync GEMM with hi/lo compensation -----------------
// out = X @ W (+epilogues).  epi: 0=none; 1=relu(acc+bias); 2=acc+bias+add[row]
// acc += Ahi*Bhi + Ahi*Blo + Alo*Bhi  (rel err ~1e-6)
__device__ __forceinline__ void mma_tf32(float* d, unsigned a0, unsigned a1,
                                         unsigned a2, unsigned a3,
                                         unsigned b0, unsigned b1) {
    asm volatile(
        "mma.sync.aligned.m16n8k8.row.col.f32.tf32.tf32.f32 "
        "{%0,%1,%2,%3}, {%4,%5,%6,%7}, {%8,%9}, {%0,%1,%2,%3};"
        : "+f"(d[0]), "+f"(d[1]), "+f"(d[2]), "+f"(d[3])
        : "r"(a0), "r"(a1), "r"(a2), "r"(a3), "r"(b0), "r"(b1));
}

__device__ __forceinline__ void split_bits(float v, unsigned& hi, unsigned& lo) {
    hi = __float_as_uint(v) & 0xFFFFE000u;
    lo = __float_as_uint(v - __uint_as_float(hi));
}

__global__ void gemm_kernel(const float* __restrict__ X, const float* __restrict__ W,
                            const float* __restrict__ bias, const float* __restrict__ add,
                            float* __restrict__ out, int M, int epi) {
    extern __shared__ float sm[];
    float* Ws = sm;               // 128 x LDW
    float* Xs = sm + D * LDW;     // 128 x LDW (reused as Obuf after mainloop)

    int row0 = blockIdx.x * BM;
    int tid  = threadIdx.x;
    int wid  = tid >> 5;
    int lane = tid & 31;
    int quad = lane >> 2;         // 0..7
    int qt   = lane & 3;          // 0..3

    // stage W (full 128x128) into padded smem, coalesced
    const float4* W4 = (const float4*)W;
    for (int i = tid; i < D * DV; i += 256) {
        int r = i >> 5, c4 = i & 31;
        *(float4*)(Ws + r * LDW + c4 * 4) = W4[r * DV + c4];
    }
    // stage X tile (guard rows)
    const float4* X4 = (const float4*)X;
    for (int i = tid; i < BM * DV; i += 256) {
        int r = i >> 5, c4 = i & 31;
        int gr = row0 + r;
        float4 v = make_float4(0.f, 0.f, 0.f, 0.f);
        if (gr < M) v = X4[gr * DV + c4];
        *(float4*)(Xs + r * LDW + c4 * 4) = v;
    }
    __syncthreads();

    // warp computes rows [wid*16, wid*16+16) x all 128 cols (16 n-tiles)
    float acc[16][4];
    #pragma unroll
    for (int nt = 0; nt < 16; ++nt)
        #pragma unroll
        for (int j = 0; j < 4; ++j) acc[nt][j] = 0.f;

    const float* xb0 = Xs + (wid * 16 + quad) * LDW + qt;
    const float* xb1 = xb0 + 8 * LDW;

    for (int ks = 0; ks < 16; ++ks) {
        int k0 = ks * 8;
        float a0f = xb0[k0], a2f = xb0[k0 + 4];
        float a1f = xb1[k0], a3f = xb1[k0 + 4];
        unsigned ah0, al0, ah1, al1, ah2, al2, ah3, al3;
        split_bits(a0f, ah0, al0);
        split_bits(a1f, ah1, al1);
        split_bits(a2f, ah2, al2);
        split_bits(a3f, ah3, al3);

        const float* wk0 = Ws + (k0 + qt) * LDW + quad;       // b0: k row
        const float* wk1 = wk0 + 4 * LDW;                      // b1: k+4 row
        #pragma unroll
        for (int nt = 0; nt < 16; ++nt) {
            float b0f = wk0[nt * 8];
            float b1f = wk1[nt * 8];
            unsigned bh0, bl0, bh1, bl1;
            split_bits(b0f, bh0, bl0);
            split_bits(b1f, bh1, bl1);
            mma_tf32(acc[nt], ah0, ah1, ah2, ah3, bh0, bh1);
            mma_tf32(acc[nt], ah0, ah1, ah2, ah3, bl0, bl1);
            mma_tf32(acc[nt], al0, al1, al2, al3, bh0, bh1);
        }
    }
    __syncthreads();   // everyone done reading Xs

    // stash accumulators into Xs (as Obuf) for a clean coalesced epilogue
    {
        float* ob0 = Xs + (wid * 16 + quad) * LDW + 2 * qt;
        float* ob1 = ob0 + 8 * LDW;
        #pragma unroll
        for (int nt = 0; nt < 16; ++nt) {
            *(float2*)(ob0 + nt * 8) = make_float2(acc[nt][0], acc[nt][1]);
            *(float2*)(ob1 + nt * 8) = make_float2(acc[nt][2], acc[nt][3]);
        }
    }
    __syncthreads();

    const float4* add4 = (const float4*)add;
    float4* out4 = (float4*)out;
    for (int i = tid; i < BM * DV; i += 256) {
        int r = i >> 5, c4 = i & 31;
        int gr = row0 + r;
        if (gr >= M) continue;
        float4 o = *(float4*)(Xs + r * LDW + c4 * 4);
        if (epi != 0) {
            float4 b = ((const float4*)bias)[c4];
            o.x += b.x; o.y += b.y; o.z += b.z; o.w += b.w;
        }
        if (epi == 1) {
            o.x = fmaxf(o.x, 0.f); o.y = fmaxf(o.y, 0.f);
            o.z = fmaxf(o.z, 0.f); o.w = fmaxf(o.w, 0.f);
        } else if (epi == 2) {
            float4 a = add4[gr * DV + c4];
            o.x += a.x; o.y += a.y; o.z += a.z; o.w += a.w;
        }
        out4[gr * DV + c4] = o;
    }
}

// ---------------- fused aggregation + bias + LayerNorm (+ReLU) ---------------
// warp per node: out[v] = LN( dinv[v]^2*h[v] + sum_in norm*h[u] + bias )
__global__ void agg_ln_kernel(const float* __restrict__ h, const float* __restrict__ bias,
                              const float* __restrict__ gamma, const float* __restrict__ beta,
                              float* __restrict__ out, int N, int doRelu) {
    int gw   = (blockIdx.x * blockDim.x + threadIdx.x) >> 5;
    int lane = threadIdx.x & 31;
    if (gw >= N) return;
    int v = gw;

    const float4* h4 = (const float4*)h;
    float dv = g_dinv[v];
    float ds = dv * dv;
    float4 acc = h4[v * DV + lane];
    acc.x *= ds; acc.y *= ds; acc.z *= ds; acc.w *= ds;

    int s = g_rowstart[v];
    int e = g_rowstart[v + 1];
    for (int j = s; j < e; ++j) {
        int u   = g_csr_src[j];
        float n = g_csr_norm[j];
        float4 hv = h4[u * DV + lane];
        acc.x += hv.x * n; acc.y += hv.y * n;
        acc.z += hv.z * n; acc.w += hv.w * n;
    }

    float4 bv = ((const float4*)bias)[lane];
    acc.x += bv.x; acc.y += bv.y; acc.z += bv.z; acc.w += bv.w;

    // mean over 128
    float sum = acc.x + acc.y + acc.z + acc.w;
    #pragma unroll
    for (int o = 16; o > 0; o >>= 1) sum += __shfl_xor_sync(0xffffffffu, sum, o);
    float mu = sum * (1.0f / 128.0f);

    float cx = acc.x - mu, cy = acc.y - mu, cz = acc.z - mu, cw = acc.w - mu;
    float sq = cx * cx + cy * cy + cz * cz + cw * cw;
    #pragma unroll
    for (int o = 16; o > 0; o >>= 1) sq += __shfl_xor_sync(0xffffffffu, sq, o);
    float rs = rsqrtf(sq * (1.0f / 128.0f) + 1e-5f);

    float4 gv  = ((const float4*)gamma)[lane];
    float4 bev = ((const float4*)beta)[lane];
    float4 o;
    o.x = cx * rs * gv.x + bev.x;
    o.y = cy * rs * gv.y + bev.y;
    o.z = cz * rs * gv.z + bev.z;
    o.w = cw * rs * gv.w + bev.w;
    if (doRelu) {
        o.x = fmaxf(o.x, 0.f); o.y = fmaxf(o.y, 0.f);
        o.z = fmaxf(o.z, 0.f); o.w = fmaxf(o.w, 0.f);
    }
    ((float4*)out)[v * DV + lane] = o;
}

// ---------------- driver -----------------------------------------------------
extern "C" void kernel_launch(void* const* d_in, const int* in_sizes, int n_in,
                              void* d_out, int out_size) {
    const int*   edge_index = (const int*)d_in[0];
    const float* ent = (const float*)d_in[1];
    const float* W1  = (const float*)d_in[2];
    const float* b1  = (const float*)d_in[3];
    const float* g1  = (const float*)d_in[4];
    const float* be1 = (const float*)d_in[5];
    const float* W2  = (const float*)d_in[6];
    const float* b2  = (const float*)d_in[7];
    const float* g2  = (const float*)d_in[8];
    const float* be2 = (const float*)d_in[9];
    const float* W3  = (const float*)d_in[10];
    const float* b3  = (const float*)d_in[11];
    const float* g3  = (const float*)d_in[12];
    const float* be3 = (const float*)d_in[13];
    const float* Wt1 = (const float*)d_in[14];
    const float* bt1 = (const float*)d_in[15];
    const float* Wt2 = (const float*)d_in[16];
    const float* bt2 = (const float*)d_in[17];

    int E = in_sizes[0] / 2;
    int N = in_sizes[1] / D;
    const int* src = edge_index;
    const int* dst = edge_index + E;

    float *ph, *px, *py;
    cudaGetSymbolAddress((void**)&ph, g_h);
    cudaGetSymbolAddress((void**)&px, g_x);
    cudaGetSymbolAddress((void**)&py, g_y);

    const int SMEM = 2 * D * LDW * sizeof(float);   // 2*128*136*4 = 139264 B
    cudaFuncSetAttribute(gemm_kernel, cudaFuncAttributeMaxDynamicSharedMemorySize, SMEM);

    int nb  = (N + 255) / 256;
    int eb  = (E + 255) / 256;
    int gg  = (N + BM - 1) / BM;
    int ab  = (N * 32 + 255) / 256;
    int sb  = (N + 4095) / 4096;

    // graph preprocessing (CSR by dst, symmetric normalization)
    zero_deg_kernel<<<nb, 256>>>(N);
    count_deg_kernel<<<eb, 256>>>(dst, E);
    dinv_kernel<<<nb, 256>>>(N);
    scan_part_kernel<<<sb, 256>>>(N);
    scan_final_kernel<<<sb, 1024>>>(N, sb);
    fill_kernel<<<eb, 256>>>(src, dst, E);

    // layer 1
    gemm_kernel<<<gg, 256, SMEM>>>(ent, W1, nullptr, nullptr, ph, N, 0);
    agg_ln_kernel<<<ab, 256>>>(ph, b1, g1, be1, px, N, 1);
    // layer 2
    gemm_kernel<<<gg, 256, SMEM>>>(px, W2, nullptr, nullptr, ph, N, 0);
    agg_ln_kernel<<<ab, 256>>>(ph, b2, g2, be2, py, N, 1);
    // layer 3 (LN, no relu)
    gemm_kernel<<<gg, 256, SMEM>>>(py, W3, nullptr, nullptr, ph, N, 0);
    agg_ln_kernel<<<ab, 256>>>(ph, b3, g3, be3, px, N, 0);
    // transform MLP + residual with x0
    gemm_kernel<<<gg, 256, SMEM>>>(px, Wt1, bt1, nullptr, py, N, 1);
    gemm_kernel<<<gg, 256, SMEM>>>(py, Wt2, bt2, ent, (float*)d_out, N, 2);
}

// round 8
// speedup vs baseline: 1.4635x; 1.4584x over previous
#include <cuda_runtime.h>
#include <cuda_fp16.h>

#define D 128
#define DV 32            // float4 per row
#define BM 64            // gemm rows per block
#define MAXN 100352
#define MAXE 1700000

// ---------------- scratch (device globals: no allocation allowed) -------------
__device__ unsigned g_h16[MAXN * 64];   // half2-packed pre-scaled hidden (25.7MB)
__device__ float g_x[MAXN * D];
__device__ float g_y[MAXN * D];
__device__ float g_dinv[MAXN];
__device__ int   g_deg[MAXN];
__device__ int   g_rowstart[MAXN + 1];
__device__ int   g_cursor[MAXN];
__device__ int   g_csr_src[MAXE];
__device__ int   g_part[64];

// ---------------- packed f32x2 helpers (Blackwell FFMA2 path) ----------------
__device__ __forceinline__ unsigned long long pack2(float a, float b) {
    unsigned long long r;
    asm("mov.b64 %0, {%1, %2};" : "=l"(r) : "f"(a), "f"(b));
    return r;
}
__device__ __forceinline__ void unpack2(unsigned long long v, float& a, float& b) {
    asm("mov.b64 {%0, %1}, %2;" : "=f"(a), "=f"(b) : "l"(v));
}
__device__ __forceinline__ unsigned long long ffma2(unsigned long long a,
                                                    unsigned long long b,
                                                    unsigned long long c) {
    unsigned long long d;
    asm("fma.rn.f32x2 %0, %1, %2, %3;" : "=l"(d) : "l"(a), "l"(b), "l"(c));
    return d;
}

// ---------------- degree / normalization ------------------------------------
__global__ void zero_deg_kernel(int n) {
    int i = blockIdx.x * blockDim.x + threadIdx.x;
    if (i < n) g_deg[i] = 0;
}

__global__ void count_deg_kernel(const int* __restrict__ dst, int E) {
    int e = blockIdx.x * blockDim.x + threadIdx.x;
    if (e < E) atomicAdd(&g_deg[dst[e]], 1);
}

__global__ void dinv_kernel(int n) {
    int i = blockIdx.x * blockDim.x + threadIdx.x;
    if (i < n) g_dinv[i] = rsqrtf((float)(g_deg[i] + 1));
}

// ---- multi-block scan: pass 1, per-block (4096 elems) partial sums ----------
__global__ void scan_part_kernel(int n) {
    int base = blockIdx.x * 4096;
    int sum = 0;
    for (int i = threadIdx.x; i < 4096; i += 256) {
        int idx = base + i;
        if (idx < n) sum += g_deg[idx];
    }
    #pragma unroll
    for (int o = 16; o > 0; o >>= 1) sum += __shfl_xor_sync(0xffffffffu, sum, o);
    __shared__ int ws[8];
    if ((threadIdx.x & 31) == 0) ws[threadIdx.x >> 5] = sum;
    __syncthreads();
    if (threadIdx.x == 0) {
        int t = 0;
        #pragma unroll
        for (int w = 0; w < 8; ++w) t += ws[w];
        g_part[blockIdx.x] = t;
    }
}

// ---- pass 2: per-block exclusive scan of its 4096 chunk + global offset -----
__global__ void scan_final_kernel(int n, int nblocks) {
    __shared__ int s_off;
    __shared__ int warp_sums[32];
    int tid = threadIdx.x;                  // 1024 threads
    int base = blockIdx.x * 4096;
    if (tid == 0) {
        int off = 0;
        for (int b = 0; b < blockIdx.x; ++b) off += g_part[b];
        s_off = off;
        if (blockIdx.x == 0) {
            int tot = 0;
            for (int b = 0; b < nblocks; ++b) tot += g_part[b];
            g_rowstart[n] = tot;
        }
    }
    __syncthreads();

    int i0 = base + tid * 4;
    int v[4];
    int s = 0;
    #pragma unroll
    for (int k = 0; k < 4; ++k) {
        int idx = i0 + k;
        v[k] = (idx < n) ? g_deg[idx] : 0;
        s += v[k];
    }
    int lane = tid & 31, wid = tid >> 5;
    int x = s;
    #pragma unroll
    for (int o = 1; o < 32; o <<= 1) {
        int y = __shfl_up_sync(0xffffffffu, x, o);
        if (lane >= o) x += y;
    }
    if (lane == 31) warp_sums[wid] = x;
    __syncthreads();
    if (wid == 0) {
        int w = warp_sums[lane];
        #pragma unroll
        for (int o = 1; o < 32; o <<= 1) {
            int y = __shfl_up_sync(0xffffffffu, w, o);
            if (lane >= o) w += y;
        }
        warp_sums[lane] = w;
    }
    __syncthreads();
    int excl = x - s + ((wid > 0) ? warp_sums[wid - 1] : 0) + s_off;
    #pragma unroll
    for (int k = 0; k < 4; ++k) {
        int idx = i0 + k;
        if (idx < n) {
            g_rowstart[idx] = excl;
            g_cursor[idx]   = excl;
            excl += v[k];
        }
    }
}

__global__ void fill_kernel(const int* __restrict__ src, const int* __restrict__ dst, int E) {
    int e = blockIdx.x * blockDim.x + threadIdx.x;
    if (e >= E) return;
    int u = src[e], v = dst[e];
    int slot = atomicAdd(&g_cursor[v], 1);
    g_csr_src[slot] = u;
}

// ---------------- GEMM: out = X @ W (+epilogues), packed f32x2 FMA -----------
// epi: 1 = relu(acc + bias) -> fp32 out; 2 = acc + bias + add[row] -> fp32 out
// epi: 3 = write half2( dinv[row] * acc ) into h16 buffer (pre-scaled gather payload)
__global__ void gemm_kernel(const float* __restrict__ X, const float* __restrict__ W,
                            const float* __restrict__ bias, const float* __restrict__ add,
                            float* __restrict__ out, unsigned* __restrict__ out16,
                            int M, int epi) {
    extern __shared__ float sm[];
    float* Ws = sm;              // 128*128
    float* Xs = sm + D * D;      // BM*128
    int row0 = blockIdx.x * BM;

    // load full W (64KB)
    const float4* W4 = (const float4*)W;
    float4* Ws4w = (float4*)Ws;
    for (int i = threadIdx.x; i < D * D / 4; i += 256) Ws4w[i] = W4[i];

    // load X tile (guard rows)
    const float4* X4 = (const float4*)X;
    float4* Xs4 = (float4*)Xs;
    for (int i = threadIdx.x; i < BM * D / 4; i += 256) {
        int r = i >> 5;           // 32 float4 per row
        int c = i & 31;
        int gr = row0 + r;
        float4 v = make_float4(0.f, 0.f, 0.f, 0.f);
        if (gr < M) v = X4[gr * DV + c];
        Xs4[i] = v;
    }
    __syncthreads();

    int tx = threadIdx.x & 31;    // cols 4*tx .. 4*tx+3
    int ty = threadIdx.x >> 5;    // rows ty*8 .. ty*8+7

    unsigned long long acc2[8][2];
    #pragma unroll
    for (int r = 0; r < 8; ++r) { acc2[r][0] = 0ull; acc2[r][1] = 0ull; }

    const float4* Ws4 = (const float4*)Ws;
    const float* Xrow = Xs + (ty * 8) * D;

    #pragma unroll 4
    for (int k = 0; k < D; ++k) {
        float4 w = Ws4[k * DV + tx];
        unsigned long long wxy = pack2(w.x, w.y);
        unsigned long long wzw = pack2(w.z, w.w);
        #pragma unroll
        for (int r = 0; r < 8; ++r) {
            float xv = Xrow[r * D + k];
            unsigned long long xx = pack2(xv, xv);
            acc2[r][0] = ffma2(xx, wxy, acc2[r][0]);
            acc2[r][1] = ffma2(xx, wzw, acc2[r][1]);
        }
    }

    if (epi == 3) {
        // pre-scaled fp16 output: hs[row] = dinv[row] * acc
        #pragma unroll
        for (int r = 0; r < 8; ++r) {
            int gr = row0 + ty * 8 + r;
            if (gr >= M) continue;
            float s = g_dinv[gr];
            float4 o;
            unpack2(acc2[r][0], o.x, o.y);
            unpack2(acc2[r][1], o.z, o.w);
            __half2 h0 = __floats2half2_rn(o.x * s, o.y * s);
            __half2 h1 = __floats2half2_rn(o.z * s, o.w * s);
            uint2 pk = make_uint2(*(unsigned*)&h0, *(unsigned*)&h1);
            *(uint2*)(out16 + gr * 64 + 2 * tx) = pk;
        }
        return;
    }

    float4 bv = ((const float4*)bias)[tx];
    float4* out4 = (float4*)out;
    const float4* add4 = (const float4*)add;

    #pragma unroll
    for (int r = 0; r < 8; ++r) {
        int gr = row0 + ty * 8 + r;
        if (gr >= M) continue;
        float4 o;
        unpack2(acc2[r][0], o.x, o.y);
        unpack2(acc2[r][1], o.z, o.w);
        o.x += bv.x; o.y += bv.y; o.z += bv.z; o.w += bv.w;
        if (epi == 1) {
            o.x = fmaxf(o.x, 0.f); o.y = fmaxf(o.y, 0.f);
            o.z = fmaxf(o.z, 0.f); o.w = fmaxf(o.w, 0.f);
        } else {
            float4 a = add4[gr * DV + tx];
            o.x += a.x; o.y += a.y; o.z += a.z; o.w += a.w;
        }
        out4[gr * DV + tx] = o;
    }
}

// ---------------- fused aggregation + bias + LayerNorm (+ReLU) ---------------
// warp per node, fp16 pre-scaled payload:
// out[v] = LN( dinv[v] * ( hs[v] + sum_{u->v} hs[u] ) + bias )
__global__ void agg_ln_kernel(const unsigned* __restrict__ h16,
                              const float* __restrict__ bias,
                              const float* __restrict__ gamma, const float* __restrict__ beta,
                              float* __restrict__ out, int N, int doRelu) {
    int gw   = (blockIdx.x * blockDim.x + threadIdx.x) >> 5;
    int lane = threadIdx.x & 31;
    if (gw >= N) return;
    int v = gw;

    // self term
    uint2 pk = *(const uint2*)(h16 + v * 64 + 2 * lane);
    float2 f0 = __half22float2(*(__half2*)&pk.x);
    float2 f1 = __half22float2(*(__half2*)&pk.y);
    float4 acc = make_float4(f0.x, f0.y, f1.x, f1.y);

    int s = g_rowstart[v];
    int e = g_rowstart[v + 1];
    for (int j = s; j < e; ++j) {
        int u = g_csr_src[j];
        uint2 p = *(const uint2*)(h16 + u * 64 + 2 * lane);
        float2 a = __half22float2(*(__half2*)&p.x);
        float2 b = __half22float2(*(__half2*)&p.y);
        acc.x += a.x; acc.y += a.y; acc.z += b.x; acc.w += b.y;
    }

    float dv = g_dinv[v];
    float4 bv = ((const float4*)bias)[lane];
    acc.x = acc.x * dv + bv.x;
    acc.y = acc.y * dv + bv.y;
    acc.z = acc.z * dv + bv.z;
    acc.w = acc.w * dv + bv.w;

    // mean over 128
    float sum = acc.x + acc.y + acc.z + acc.w;
    #pragma unroll
    for (int o = 16; o > 0; o >>= 1) sum += __shfl_xor_sync(0xffffffffu, sum, o);
    float mu = sum * (1.0f / 128.0f);

    float cx = acc.x - mu, cy = acc.y - mu, cz = acc.z - mu, cw = acc.w - mu;
    float sq = cx * cx + cy * cy + cz * cz + cw * cw;
    #pragma unroll
    for (int o = 16; o > 0; o >>= 1) sq += __shfl_xor_sync(0xffffffffu, sq, o);
    float rs = rsqrtf(sq * (1.0f / 128.0f) + 1e-5f);

    float4 gv  = ((const float4*)gamma)[lane];
    float4 bev = ((const float4*)beta)[lane];
    float4 o;
    o.x = cx * rs * gv.x + bev.x;
    o.y = cy * rs * gv.y + bev.y;
    o.z = cz * rs * gv.z + bev.z;
    o.w = cw * rs * gv.w + bev.w;
    if (doRelu) {
        o.x = fmaxf(o.x, 0.f); o.y = fmaxf(o.y, 0.f);
        o.z = fmaxf(o.z, 0.f); o.w = fmaxf(o.w, 0.f);
    }
    ((float4*)out)[v * DV + lane] = o;
}

// ---------------- driver -----------------------------------------------------
extern "C" void kernel_launch(void* const* d_in, const int* in_sizes, int n_in,
                              void* d_out, int out_size) {
    const int*   edge_index = (const int*)d_in[0];
    const float* ent = (const float*)d_in[1];
    const float* W1  = (const float*)d_in[2];
    const float* b1  = (const float*)d_in[3];
    const float* g1  = (const float*)d_in[4];
    const float* be1 = (const float*)d_in[5];
    const float* W2  = (const float*)d_in[6];
    const float* b2  = (const float*)d_in[7];
    const float* g2  = (const float*)d_in[8];
    const float* be2 = (const float*)d_in[9];
    const float* W3  = (const float*)d_in[10];
    const float* b3  = (const float*)d_in[11];
    const float* g3  = (const float*)d_in[12];
    const float* be3 = (const float*)d_in[13];
    const float* Wt1 = (const float*)d_in[14];
    const float* bt1 = (const float*)d_in[15];
    const float* Wt2 = (const float*)d_in[16];
    const float* bt2 = (const float*)d_in[17];

    int E = in_sizes[0] / 2;
    int N = in_sizes[1] / D;
    const int* src = edge_index;
    const int* dst = edge_index + E;

    float *px, *py;
    unsigned *ph16;
    cudaGetSymbolAddress((void**)&ph16, g_h16);
    cudaGetSymbolAddress((void**)&px, g_x);
    cudaGetSymbolAddress((void**)&py, g_y);

    const int SMEM = (D * D + BM * D) * sizeof(float);   // 96 KB
    cudaFuncSetAttribute(gemm_kernel, cudaFuncAttributeMaxDynamicSharedMemorySize, SMEM);

    int nb  = (N + 255) / 256;
    int eb  = (E + 255) / 256;
    int gg  = (N + BM - 1) / BM;
    int ab  = (N * 32 + 255) / 256;
    int sb  = (N + 4095) / 4096;

    // graph preprocessing (CSR by dst, symmetric normalization)
    zero_deg_kernel<<<nb, 256>>>(N);
    count_deg_kernel<<<eb, 256>>>(dst, E);
    dinv_kernel<<<nb, 256>>>(N);
    scan_part_kernel<<<sb, 256>>>(N);
    scan_final_kernel<<<sb, 1024>>>(N, sb);
    fill_kernel<<<eb, 256>>>(src, dst, E);

    // layer 1
    gemm_kernel<<<gg, 256, SMEM>>>(ent, W1, nullptr, nullptr, nullptr, ph16, N, 3);
    agg_ln_kernel<<<ab, 256>>>(ph16, b1, g1, be1, px, N, 1);
    // layer 2
    gemm_kernel<<<gg, 256, SMEM>>>(px, W2, nullptr, nullptr, nullptr, ph16, N, 3);
    agg_ln_kernel<<<ab, 256>>>(ph16, b2, g2, be2, py, N, 1);
    // layer 3 (LN, no relu)
    gemm_kernel<<<gg, 256, SMEM>>>(py, W3, nullptr, nullptr, nullptr, ph16, N, 3);
    agg_ln_kernel<<<ab, 256>>>(ph16, b3, g3, be3, px, N, 0);
    // transform MLP + residual with x0
    gemm_kernel<<<gg, 256, SMEM>>>(px, Wt1, bt1, nullptr, py, nullptr, N, 1);
    gemm_kernel<<<gg, 256, SMEM>>>(py, Wt2, bt2, ent, (float*)d_out, nullptr, N, 2);
}